// round 11
// baseline (speedup 1.0000x reference)
#include <cuda_runtime.h>
#include <cuda_bf16.h>
#include <math.h>

// Problem constants (fixed by setup_inputs)
#define Bsz 2
#define Hh  64
#define Ww  64
#define Ls  4096      // H*W
#define Cc  96
#define Kk  4
#define Nn  16
#define Rr  6
#define Sseg 256      // segments
#define Tseg 16       // steps per segment (Sseg*Tseg = L)

// ---------------- scratch (static device globals; no allocation) -------------
__device__ float  g_v[Bsz*Cc*Ls];          // v_img (b,c,l)   l = h*64+w
__device__ float  g_vw[Bsz*Cc*Ls];         // transposed      t = w*64+h -> v[h*64+w]
__device__ float  g_Cv[Bsz*Kk*Ls*Nn];      // C (b,k,t,n)
__device__ float  g_y[Bsz*Kk*Ls*Cc];       // y_local then corrected (b,k,t,c)
__device__ float  g_W[Bsz*Kk*Ls*Cc];       // W(t) = exp(A0 * cumsum(delta)) within segment
__device__ float  g_hend[Bsz*Kk*Sseg*Cc*Nn];
__device__ float  g_h0[Bsz*Kk*Sseg*Cc*Nn];
__device__ float  g_sumd[Bsz*Kk*Sseg*Cc];
__device__ float  g_convx[Bsz*Cc*Ls];      // (b,c,l)
__device__ float  g_pool[Bsz*Cc];
// A-matrix prep (per k*Cc+c)
__device__ float  g_A0[Kk*Cc];
__device__ float  g_fastf[Kk*Cc];
__device__ float  g_An[Kk*Cc*Nn];

__device__ __forceinline__ float sigmoidf_(float x){ return 1.0f/(1.0f+__expf(-x)); }

// ---------------- K1: v_img = (x @ qkv_w^T) -> (b,c,l)  (+ A prep block) -----
__global__ void k_qkv(const float* __restrict__ x, const float* __restrict__ qkv_w,
                      const float* __restrict__ A_logs)
{
    __shared__ float sx[32][97];
    __shared__ float sw[96][97];
    int blk = blockIdx.x;
    int tid = threadIdx.x;       // 192

    if (blk == Bsz*(Ls/32)) {    // prep block: A0 / fast flag / An per (k,c)
        for (int kc = tid; kc < Kk*Cc; kc += 192) {
            float A[16];
            #pragma unroll
            for (int n = 0; n < 16; n++) A[n] = -__expf(A_logs[kc*Nn + n]);
            float fast = 1.0f;
            #pragma unroll
            for (int n = 1; n < 16; n++) {
                float expect = (float)(n+1);
                if (fabsf(A[n]/A[0] - expect) > 1e-5f*expect) fast = 0.0f;
            }
            g_A0[kc] = A[0];
            g_fastf[kc] = fast;
            #pragma unroll
            for (int n = 0; n < 16; n++) g_An[kc*Nn + n] = A[n];
        }
        return;
    }

    int b   = blk / (Ls/32);
    int l0  = (blk % (Ls/32)) * 32;
    int c    = tid % 96;
    int half = tid / 96;

    for (int idx = tid; idx < 96*96; idx += 192)
        sw[idx/96][idx%96] = qkv_w[idx];
    for (int i = half; i < 32; i += 2)
        sx[i][c] = x[(b*Ls + l0 + i)*Cc + c];
    __syncthreads();

    for (int l = half*16; l < half*16 + 16; l += 4) {
        float a0=0.f,a1=0.f,a2=0.f,a3=0.f;
        #pragma unroll
        for (int cp = 0; cp < 96; cp++) {
            float wv = sw[c][cp];
            a0 += sx[l+0][cp]*wv;
            a1 += sx[l+1][cp]*wv;
            a2 += sx[l+2][cp]*wv;
            a3 += sx[l+3][cp]*wv;
        }
        float4 o = make_float4(a0,a1,a2,a3);
        *reinterpret_cast<float4*>(&g_v[(b*Cc + c)*Ls + l0 + l]) = o;
    }
}

// ---------------- K1b: per-plane 64x64 transpose -> g_vw ---------------------
__global__ void k_tr()
{
    __shared__ float s[64][65];
    int plane = blockIdx.x;             // b*Cc + c  (192 planes)
    const float* src = &g_v[plane*Ls];
    float*       dst = &g_vw[plane*Ls];
    int tid = threadIdx.x;              // 256
    for (int idx = tid; idx < 4096; idx += 256)
        s[idx>>6][idx&63] = src[idx];
    __syncthreads();
    for (int idx = tid; idx < 4096; idx += 256)
        dst[idx] = s[idx&63][idx>>6];   // dst[w*64+h] = v[h*64+w]
}

// ---------------- K2: projections + fused local scan (pass A + y_local) ------
__global__ void k_proj(const float* __restrict__ x_proj_w,
                       const float* __restrict__ dt_w,
                       const float* __restrict__ dt_b)
{
    __shared__ float sxs[32][97];
    __shared__ float swp[38][97];
    __shared__ float sxd[32][40];

    int tiles = Ls/32;
    int tile = blockIdx.x % tiles;
    int k    = (blockIdx.x / tiles) % Kk;
    int b    = blockIdx.x / (tiles*Kk);
    int tid  = threadIdx.x;   // 192
    int c    = tid % 96;
    int half = tid / 96;
    int t0   = tile*32;

    for (int idx = tid; idx < 38*96; idx += 192)
        swp[idx/96][idx%96] = x_proj_w[k*38*96 + idx];
    float wdt[6];
    #pragma unroll
    for (int r = 0; r < 6; r++) wdt[r] = dt_w[(k*Cc + c)*Rr + r];
    float dtb = dt_b[k*Cc + c];
    int   kc  = k*Cc + c;
    float A0  = g_A0[kc];
    bool  fast = (g_fastf[kc] != 0.0f);

    // per-thread contiguous row loads in scan order (each half loads 16 rows)
    const float* srcp = ((k & 1) ? g_vw : g_v) + (b*Cc + c)*Ls;
    if (k < 2) {
        const float4* p4 = reinterpret_cast<const float4*>(srcp + t0 + half*16);
        #pragma unroll
        for (int j = 0; j < 4; j++) {
            float4 v4 = p4[j];
            int r0 = half*16 + 4*j;
            sxs[r0+0][c]=v4.x; sxs[r0+1][c]=v4.y; sxs[r0+2][c]=v4.z; sxs[r0+3][c]=v4.w;
        }
    } else {
        const float4* p4 = reinterpret_cast<const float4*>(srcp + (4096 - t0 - 32) + half*16);
        #pragma unroll
        for (int j = 0; j < 4; j++) {
            float4 v4 = p4[j];
            int ib = 31 - (half*16 + 4*j);
            sxs[ib][c]=v4.x; sxs[ib-1][c]=v4.y; sxs[ib-2][c]=v4.z; sxs[ib-3][c]=v4.w;
        }
    }
    __syncthreads();

    // x_dbl = xs @ x_proj_w^T : 38*8 = 304 tasks
    for (int p = tid; p < 38*8; p += 192) {
        int j = p % 38, i0 = (p / 38)*4;
        float a0=0.f,a1=0.f,a2=0.f,a3=0.f;
        #pragma unroll
        for (int cp = 0; cp < 96; cp++) {
            float wv = swp[j][cp];
            a0 += sxs[i0+0][cp]*wv;
            a1 += sxs[i0+1][cp]*wv;
            a2 += sxs[i0+2][cp]*wv;
            a3 += sxs[i0+3][cp]*wv;
        }
        sxd[i0+0][j]=a0; sxd[i0+1][j]=a1; sxd[i0+2][j]=a2; sxd[i0+3][j]=a3;
    }
    __syncthreads();

    int bk = b*Kk + k;
    // fused local scan: this half-tile IS segment (tile*2 + half), h0 = 0
    float h[16];
    #pragma unroll
    for (int n = 0; n < 16; n++) h[n] = 0.f;
    float cum = 0.f;
    float Wrun = 1.f;

    #pragma unroll
    for (int ii = 0; ii < 16; ii++) {
        int i = half*16 + ii;
        float acc = dtb;
        #pragma unroll
        for (int r = 0; r < 6; r++) acc += sxd[i][r]*wdt[r];
        float delta = (acc > 20.f) ? acc : log1pf(__expf(acc));
        cum += delta;
        float du = delta * sxs[i][c];
        float w = __expf(delta * A0);
        Wrun *= w;
        float dA[16];
        if (fast) {
            float w2 = w*w, w4 = w2*w2, w8 = w4*w4;
            dA[0]=w;      dA[1]=w2;     dA[2]=w2*w;    dA[3]=w4;
            dA[4]=w4*w;   dA[5]=w4*w2;  dA[6]=dA[5]*w; dA[7]=w8;
            #pragma unroll
            for (int n = 0; n < 8; n++) dA[8+n] = w8*dA[n];
        } else {
            #pragma unroll
            for (int n = 0; n < 16; n++) dA[n] = __expf(delta * g_An[kc*Nn + n]);
        }
        float y0=0.f,y1=0.f,y2=0.f,y3=0.f;
        #pragma unroll
        for (int n = 0; n < 16; n += 4) {
            h[n+0] = dA[n+0]*h[n+0] + du*sxd[i][6+n+0];
            h[n+1] = dA[n+1]*h[n+1] + du*sxd[i][6+n+1];
            h[n+2] = dA[n+2]*h[n+2] + du*sxd[i][6+n+2];
            h[n+3] = dA[n+3]*h[n+3] + du*sxd[i][6+n+3];
            y0 += h[n+0]*sxd[i][22+n+0];
            y1 += h[n+1]*sxd[i][22+n+1];
            y2 += h[n+2]*sxd[i][22+n+2];
            y3 += h[n+3]*sxd[i][22+n+3];
        }
        int gi = (bk*Ls + t0 + i);
        g_y[gi*Cc + c] = (y0+y1) + (y2+y3);
        g_W[gi*Cc + c] = Wrun;
    }

    int hb = (bk*Sseg + tile*2 + half)*Cc + c;
    g_sumd[hb] = cum;
    float4* hp = reinterpret_cast<float4*>(&g_hend[hb*Nn]);
    #pragma unroll
    for (int q = 0; q < 4; q++)
        hp[q] = make_float4(h[4*q], h[4*q+1], h[4*q+2], h[4*q+3]);

    // store C for the correction kernel
    for (int p = tid; p < 32*16; p += 192) {
        int i = p / 16, n = p % 16;
        int gi = (bk*Ls + t0 + i);
        g_Cv[gi*Nn + n] = sxd[i][22 + n];
    }
}

// ---------------- K3b: combine — per-channel block-staged affine scan --------
// one block (256 thr) per (bk, c). 16 groups x 16 segments; 1 exp per segment.
__global__ void k_combine()
{
    __shared__ float sE[Sseg][17];    // hend, then h0 (in place) ~17 KB
    __shared__ float sW[Sseg];        // w = exp(A0*sumd)
    __shared__ float sSd[Sseg];       // sumd (non-fast fallback)
    __shared__ float sA[16][17];
    __shared__ float sB[16][17];
    __shared__ float sH[16][17];

    int bk = blockIdx.x / Cc;         // 0..7
    int c  = blockIdx.x % Cc;
    int k  = bk & 3;
    int tid = threadIdx.x;            // 256
    float A0 = g_A0[k*Cc + c];

    // coalesced load of hend (64B per segment row)
    for (int p = tid; p < Sseg*16; p += 256) {
        int s = p >> 4, j = p & 15;
        sE[s][j] = g_hend[((bk*Sseg + s)*Cc + c)*Nn + j];
    }
    for (int s = tid; s < Sseg; s += 256) {
        float sd = g_sumd[(bk*Sseg + s)*Cc + c];
        sSd[s] = sd;
        sW[s]  = __expf(A0 * sd);
    }
    __syncthreads();

    int n = tid & 15;                 // chain (state index)
    int g = tid >> 4;                 // segment group 0..15 (16 segs each)
    int m = n + 1;                    // power
    bool fast = (g_fastf[k*Cc + c] != 0.0f);
    float An  = g_An[(k*Cc + c)*Nn + n];
    int sbase = g*16;

    float P[16];
    if (fast) {
        #pragma unroll
        for (int j = 0; j < 16; j++) {
            float w = sW[sbase + j];
            float w2 = w*w, w4 = w2*w2, w8 = w4*w4, w16 = w8*w8;
            float p = 1.f;
            if (m & 1)  p *= w;
            if (m & 2)  p *= w2;
            if (m & 4)  p *= w4;
            if (m & 8)  p *= w8;
            if (m & 16) p *= w16;
            P[j] = p;
        }
    } else {
        #pragma unroll
        for (int j = 0; j < 16; j++) P[j] = __expf(An * sSd[sbase + j]);
    }

    // local affine compose: h_out = A*h_in + Bv over this group's 16 segments
    float A = 1.f, Bv = 0.f;
    #pragma unroll
    for (int j = 0; j < 16; j++) { Bv = P[j]*Bv + sE[sbase + j][n]; A *= P[j]; }
    sA[g][n] = A; sB[g][n] = Bv;
    __syncthreads();

    // exclusive scan over the 16 groups (16 threads, 16 serial FMAs)
    if (tid < 16) {
        float h = 0.f;
        #pragma unroll
        for (int gg = 0; gg < 16; gg++) {
            sH[gg][tid] = h;
            h = sA[gg][tid]*h + sB[gg][tid];
        }
    }
    __syncthreads();

    // propagate h0 per segment, in place in sE
    float h = sH[g][n];
    #pragma unroll
    for (int j = 0; j < 16; j++) {
        float e = sE[sbase + j][n];
        sE[sbase + j][n] = h;
        h = P[j]*h + e;
    }
    __syncthreads();

    // coalesced write-out
    for (int p = tid; p < Sseg*16; p += 256) {
        int s = p >> 4, j = p & 15;
        g_h0[((bk*Sseg + s)*Cc + c)*Nn + j] = sE[s][j];
    }
}

// ---------------- K4: parallel y correction (2 segments per block) -----------
// y(t) += sum_n C(t,n) * W(t)^(n+1) * h0_seg(n)  (fast path: no exp at all)
__global__ void k_ycorr()
{
    __shared__ float4 sC4[2][Tseg][4];

    int segp = blockIdx.x & 127;      // segment pair
    int bk   = blockIdx.x >> 7;
    int k    = bk & 3;
    int tid  = threadIdx.x;           // 192
    int c    = tid % 96;
    int sub  = tid / 96;              // 0/1
    int seg  = segp*2 + sub;
    int base = bk*Ls + seg*Tseg;
    int kc   = k*Cc + c;

    for (int idx = c; idx < Tseg*4; idx += 96) {
        int i = idx >> 2, q = idx & 3;
        sC4[sub][i][q] = reinterpret_cast<const float4*>(g_Cv)[(base + i)*4 + q];
    }

    float A0   = g_A0[kc];
    bool  fast = (g_fastf[kc] != 0.0f);
    float invA0 = 1.0f / A0;
    float An[16];
    if (!fast) {
        #pragma unroll
        for (int n = 0; n < 16; n++) An[n] = g_An[kc*Nn + n];
    }

    float h0[16];
    {
        const float4* h0p = reinterpret_cast<const float4*>(
            &g_h0[((bk*Sseg + seg)*Cc + c)*Nn]);
        #pragma unroll
        for (int q = 0; q < 4; q++) {
            float4 t = h0p[q];
            h0[4*q]=t.x; h0[4*q+1]=t.y; h0[4*q+2]=t.z; h0[4*q+3]=t.w;
        }
    }
    __syncthreads();

    #pragma unroll
    for (int i = 0; i < Tseg; i++) {
        float w = g_W[(base + i)*Cc + c];   // = exp(A0 * cum)
        float dA[16];
        if (fast) {
            float w2 = w*w, w4 = w2*w2, w8 = w4*w4;
            dA[0]=w;      dA[1]=w2;     dA[2]=w2*w;    dA[3]=w4;
            dA[4]=w4*w;   dA[5]=w4*w2;  dA[6]=dA[5]*w; dA[7]=w8;
            #pragma unroll
            for (int n = 0; n < 8; n++) dA[8+n] = w8*dA[n];
        } else {
            float cum = __logf(w) * invA0;
            #pragma unroll
            for (int n = 0; n < 16; n++) dA[n] = __expf(cum * An[n]);
        }
        const float* Cp = reinterpret_cast<const float*>(&sC4[sub][i][0]);
        float y0=0.f,y1=0.f,y2=0.f,y3=0.f;
        #pragma unroll
        for (int n = 0; n < 16; n += 4) {
            y0 += dA[n+0]*h0[n+0]*Cp[n+0];
            y1 += dA[n+1]*h0[n+1]*Cp[n+1];
            y2 += dA[n+2]*h0[n+2]*Cp[n+2];
            y3 += dA[n+3]*h0[n+3]*Cp[n+3];
        }
        g_y[(base + i)*Cc + c] += (y0+y1) + (y2+y3);
    }
}

// ---------------- K5: depthwise 3x3 + BN + GELU + pooled sum -----------------
__global__ void k_conv(const float* __restrict__ dw_w, const float* __restrict__ dw_b,
                       const float* __restrict__ bn1_g, const float* __restrict__ bn1_b)
{
    __shared__ float sIm[66][66];
    __shared__ float red[256];
    int b = blockIdx.x / Cc;
    int c = blockIdx.x % Cc;
    int tid = threadIdx.x; // 256 threads

    for (int idx = tid; idx < 66*66; idx += 256)
        (&sIm[0][0])[idx] = 0.f;
    __syncthreads();
    const float* vp = &g_v[(b*Cc + c)*Ls];
    for (int idx = tid; idx < Ls; idx += 256)
        sIm[(idx>>6) + 1][(idx & 63) + 1] = vp[idx];

    float wgt[9];
    #pragma unroll
    for (int j = 0; j < 9; j++) wgt[j] = dw_w[c*9 + j];
    float bias = dw_b[c];
    float s1 = bn1_g[c] * rsqrtf(1.0f + 1e-5f);
    float sh = bn1_b[c];
    __syncthreads();

    float lsum = 0.f;
    for (int idx = tid; idx < Ls; idx += 256) {
        int hh = idx >> 6, ww = idx & 63;
        float acc = 0.f;
        #pragma unroll
        for (int dy = 0; dy < 3; dy++)
            #pragma unroll
            for (int dx = 0; dx < 3; dx++)
                acc += sIm[hh+dy][ww+dx]*wgt[dy*3+dx];
        float xv = (acc + bias)*s1 + sh;
        float gl = xv * normcdff(xv);
        g_convx[(b*Cc + c)*Ls + idx] = gl;
        lsum += gl;
    }
    red[tid] = lsum;
    __syncthreads();
    for (int s = 128; s > 0; s >>= 1) {
        if (tid < s) red[tid] += red[tid + s];
        __syncthreads();
    }
    if (tid == 0) g_pool[b*Cc + c] = red[0];
}

// ---------------- K6: dirs + gates + output GEMM (fused, dynamic smem) -------
__global__ void k_attout(const float* __restrict__ Ds,
                      const float* __restrict__ ci_w1, const float* __restrict__ ci_b1,
                      const float* __restrict__ ci_bn_g, const float* __restrict__ ci_bn_b,
                      const float* __restrict__ ci_w2, const float* __restrict__ ci_b2,
                      const float* __restrict__ si_w1, const float* __restrict__ si_b1,
                      const float* __restrict__ si_bn_g, const float* __restrict__ si_bn_b,
                      const float* __restrict__ si_w2, const float* __restrict__ si_b2,
                      const float* __restrict__ proj_w, const float* __restrict__ proj_b,
                      float* __restrict__ out)
{
    extern __shared__ float dsm[];
    float (*sAtt)[97]   = (float(*)[97])dsm;                          // 32*97
    float (*sV)[33]     = (float(*)[33])(dsm + 32*97);                // 96*33
    float (*sCx)[33]    = (float(*)[33])(dsm + 32*97 + 96*33);        // 96*33
    float (*sProjT)[97] = (float(*)[97])(dsm + 32*97 + 2*96*33);      // 96*97
    __shared__ float spool[96];
    __shared__ float szc[12];
    __shared__ float ssw[6][96];
    __shared__ float st1[32][8];
    __shared__ float sml[32];

    int tiles = Ls/32; // 128
    int b  = blockIdx.x / tiles;
    int l0 = (blockIdx.x % tiles)*32;
    int tid = threadIdx.x; // 192
    int c    = tid % 96;
    int half = tid / 96;

    if (half == 0) spool[c] = g_pool[b*Cc + c] * (1.0f/4096.0f);
    for (int idx = tid; idx < 6*96; idx += 192)
        (&ssw[0][0])[idx] = si_w1[idx];
    for (int idx = tid; idx < 96*96; idx += 192)
        sProjT[idx % 96][idx / 96] = proj_w[idx];   // [cp][c_out]

    {   // own-column contiguous row loads (each half loads 16 of 32)
        const float4* vp = reinterpret_cast<const float4*>(&g_v[(b*Cc+c)*Ls + l0 + half*16]);
        const float4* cp = reinterpret_cast<const float4*>(&g_convx[(b*Cc+c)*Ls + l0 + half*16]);
        #pragma unroll
        for (int j = 0; j < 4; j++) {
            int r0 = half*16 + 4*j;
            float4 t = vp[j];
            sV[c][r0]=t.x; sV[c][r0+1]=t.y; sV[c][r0+2]=t.z; sV[c][r0+3]=t.w;
            float4 u = cp[j];
            sCx[c][r0]=u.x; sCx[c][r0+1]=u.y; sCx[c][r0+2]=u.z; sCx[c][r0+3]=u.w;
        }
    }
    __syncthreads();

    float Dsum = Ds[c] + Ds[Cc + c] + Ds[2*Cc + c] + Ds[3*Cc + c];
    int hh = l0 >> 6, ww0 = l0 & 63;
    int b4 = b*Kk;
    #pragma unroll
    for (int ii = 0; ii < 16; ii++) {
        int i = half*16 + ii;
        int l = l0 + i;
        int t1 = (ww0 + i)*64 + hh;
        float att =
            g_y[((b4+0)*Ls + l)*Cc + c] +
            g_y[((b4+1)*Ls + t1)*Cc + c] +
            g_y[((b4+2)*Ls + (4095 - l))*Cc + c] +
            g_y[((b4+3)*Ls + (4095 - t1))*Cc + c] +
            Dsum * sV[c][i];
        sAtt[i][c] = att;
    }
    __syncthreads();

    if (tid < 12) {
        float acc = ci_b1[tid];
        #pragma unroll
        for (int cp = 0; cp < 96; cp++) acc += ci_w1[tid*96 + cp]*spool[cp];
        float z = acc * (ci_bn_g[tid]*rsqrtf(1.0f + 1e-5f)) + ci_bn_b[tid];
        szc[tid] = z * normcdff(z);
    }
    {
        int i = tid / 6, j = tid % 6;
        float acc = si_b1[j];
        #pragma unroll
        for (int cp = 0; cp < 96; cp++) acc += sAtt[i][cp]*ssw[j][cp];
        float z = acc * (si_bn_g[j]*rsqrtf(1.0f + 1e-5f)) + si_bn_b[j];
        st1[i][j] = z * normcdff(z);
    }
    __syncthreads();

    float cmv = ci_b2[c];
    #pragma unroll
    for (int j = 0; j < 12; j++) cmv += ci_w2[c*12 + j]*szc[j];
    float cms = sigmoidf_(cmv);
    if (tid < 32) {
        float sm = si_b2[0];
        #pragma unroll
        for (int j = 0; j < 6; j++) sm += st1[tid][j]*si_w2[j];
        sml[tid] = sigmoidf_(sm);
    }
    __syncthreads();

    #pragma unroll
    for (int ii = 0; ii < 16; ii++) {
        int i = half*16 + ii;
        sAtt[i][c] = sAtt[i][c]*cms + sml[i]*sCx[c][i];
    }
    __syncthreads();

    float pb = proj_b[c];
    for (int i = half*16; i < half*16 + 16; i += 4) {
        float a0=pb,a1=pb,a2=pb,a3=pb;
        #pragma unroll
        for (int cp = 0; cp < 96; cp++) {
            float wv = sProjT[cp][c];
            a0 += sAtt[i+0][cp]*wv;
            a1 += sAtt[i+1][cp]*wv;
            a2 += sAtt[i+2][cp]*wv;
            a3 += sAtt[i+3][cp]*wv;
        }
        out[(b*Ls + l0 + i+0)*Cc + c] = a0;
        out[(b*Ls + l0 + i+1)*Cc + c] = a1;
        out[(b*Ls + l0 + i+2)*Cc + c] = a2;
        out[(b*Ls + l0 + i+3)*Cc + c] = a3;
    }
}

// ---------------- launcher ----------------------------------------------------
extern "C" void kernel_launch(void* const* d_in, const int* in_sizes, int n_in,
                              void* d_out, int out_size)
{
    const float* x        = (const float*)d_in[0];
    const float* qkv_w    = (const float*)d_in[3];
    const float* proj_w   = (const float*)d_in[4];
    const float* proj_b   = (const float*)d_in[5];
    const float* dw_w     = (const float*)d_in[6];
    const float* dw_b     = (const float*)d_in[7];
    const float* bn1_g    = (const float*)d_in[8];
    const float* bn1_b    = (const float*)d_in[9];
    const float* ci_w1    = (const float*)d_in[10];
    const float* ci_b1    = (const float*)d_in[11];
    const float* ci_bn_g  = (const float*)d_in[12];
    const float* ci_bn_b  = (const float*)d_in[13];
    const float* ci_w2    = (const float*)d_in[14];
    const float* ci_b2    = (const float*)d_in[15];
    const float* si_w1    = (const float*)d_in[16];
    const float* si_b1    = (const float*)d_in[17];
    const float* si_bn_g  = (const float*)d_in[18];
    const float* si_bn_b  = (const float*)d_in[19];
    const float* si_w2    = (const float*)d_in[20];
    const float* si_b2    = (const float*)d_in[21];
    const float* x_proj_w = (const float*)d_in[22];
    const float* dt_w     = (const float*)d_in[23];
    const float* dt_b     = (const float*)d_in[24];
    const float* A_logs   = (const float*)d_in[25];
    const float* Ds       = (const float*)d_in[26];
    float* out = (float*)d_out;

    const int ATTOUT_SMEM = (32*97 + 2*96*33 + 96*97) * 4;  // 75008 B
    cudaFuncSetAttribute(k_attout, cudaFuncAttributeMaxDynamicSharedMemorySize,
                         ATTOUT_SMEM);

    // fork/join resources — created fresh each call (kernel_launch runs only a
    // handful of times: correctness + capture). Never destroyed: the captured
    // graph may reference them. No device memory involved.
    cudaStream_t s2;
    cudaEvent_t evA, evB;
    cudaStreamCreateWithFlags(&s2, cudaStreamNonBlocking);
    cudaEventCreateWithFlags(&evA, cudaEventDisableTiming);
    cudaEventCreateWithFlags(&evB, cudaEventDisableTiming);

    // main chain (default stream, which is the captured stream)
    k_qkv<<<Bsz*(Ls/32) + 1, 192>>>(x, qkv_w, A_logs);
    cudaEventRecord(evA, 0);

    // fork: depthwise conv branch only needs g_v; joins before k_attout
    cudaStreamWaitEvent(s2, evA, 0);
    k_conv<<<Bsz*Cc, 256, 0, s2>>>(dw_w, dw_b, bn1_g, bn1_b);
    cudaEventRecord(evB, s2);

    k_tr<<<Bsz*Cc, 256>>>();
    k_proj<<<Bsz*Kk*(Ls/32), 192>>>(x_proj_w, dt_w, dt_b);
    k_combine<<<Bsz*Kk*Cc, 256>>>();
    k_ycorr<<<Bsz*Kk*(Sseg/2), 192>>>();

    cudaStreamWaitEvent((cudaStream_t)0, evB, 0);
    k_attout<<<Bsz*(Ls/32), 192, ATTOUT_SMEM>>>(Ds,
        ci_w1, ci_b1, ci_bn_g, ci_bn_b, ci_w2, ci_b2,
        si_w1, si_b1, si_bn_g, si_bn_b, si_w2, si_b2,
        proj_w, proj_b, out);
}

// round 12
// speedup vs baseline: 1.0757x; 1.0757x over previous
#include <cuda_runtime.h>
#include <cuda_bf16.h>
#include <math.h>

// Problem constants (fixed by setup_inputs)
#define Bsz 2
#define Hh  64
#define Ww  64
#define Ls  4096      // H*W
#define Cc  96
#define Kk  4
#define Nn  16
#define Rr  6
#define Sseg 256      // segments
#define Tseg 16       // steps per segment (Sseg*Tseg = L)

// ---------------- scratch (static device globals; no allocation) -------------
__device__ float  g_v[Bsz*Cc*Ls];          // v_img (b,c,l)   l = h*64+w
__device__ float  g_vw[Bsz*Cc*Ls];         // transposed      t = w*64+h -> v[h*64+w]
__device__ float  g_Cv[Bsz*Kk*Ls*Nn];      // C (b,k,t,n)
__device__ float  g_y[Bsz*Kk*Ls*Cc];       // y_local then corrected (b,k,t,c)
__device__ float  g_W[Bsz*Kk*Ls*Cc];       // W(t) = exp(A0 * cumsum(delta)) within segment
__device__ float  g_hend[Bsz*Kk*Sseg*Cc*Nn];
__device__ float  g_h0[Bsz*Kk*Sseg*Cc*Nn];
__device__ float  g_sumd[Bsz*Kk*Sseg*Cc];
__device__ float  g_convx[Bsz*Cc*Ls];      // (b,c,l)
__device__ float  g_pool[Bsz*Cc];
// A-matrix prep (per k*Cc+c)
__device__ float  g_A0[Kk*Cc];
__device__ float  g_fastf[Kk*Cc];
__device__ float  g_An[Kk*Cc*Nn];

__device__ __forceinline__ float sigmoidf_(float x){ return 1.0f/(1.0f+__expf(-x)); }

// ---------------- K1: v_img = (x @ qkv_w^T) -> (b,c,l)  (+ A prep block) -----
__global__ void k_qkv(const float* __restrict__ x, const float* __restrict__ qkv_w,
                      const float* __restrict__ A_logs)
{
    __shared__ float sx[32][100];
    __shared__ float sw[96][100];
    int blk = blockIdx.x;
    int tid = threadIdx.x;       // 192

    if (blk == Bsz*(Ls/32)) {    // prep block: A0 / fast flag / An per (k,c)
        for (int kc = tid; kc < Kk*Cc; kc += 192) {
            float A[16];
            #pragma unroll
            for (int n = 0; n < 16; n++) A[n] = -__expf(A_logs[kc*Nn + n]);
            float fast = 1.0f;
            #pragma unroll
            for (int n = 1; n < 16; n++) {
                float expect = (float)(n+1);
                if (fabsf(A[n]/A[0] - expect) > 1e-5f*expect) fast = 0.0f;
            }
            g_A0[kc] = A[0];
            g_fastf[kc] = fast;
            #pragma unroll
            for (int n = 0; n < 16; n++) g_An[kc*Nn + n] = A[n];
        }
        return;
    }

    int b   = blk / (Ls/32);
    int l0  = (blk % (Ls/32)) * 32;
    int c    = tid % 96;
    int half = tid / 96;

    for (int idx = tid; idx < 96*96; idx += 192)
        sw[idx/96][idx%96] = qkv_w[idx];
    for (int i = half; i < 32; i += 2)
        sx[i][c] = x[(b*Ls + l0 + i)*Cc + c];
    __syncthreads();

    const float4* wv4 = reinterpret_cast<const float4*>(&sw[c][0]);
    for (int l = half*16; l < half*16 + 16; l += 4) {
        const float4* x0 = reinterpret_cast<const float4*>(&sx[l+0][0]);
        const float4* x1 = reinterpret_cast<const float4*>(&sx[l+1][0]);
        const float4* x2 = reinterpret_cast<const float4*>(&sx[l+2][0]);
        const float4* x3 = reinterpret_cast<const float4*>(&sx[l+3][0]);
        float a0=0.f,a1=0.f,a2=0.f,a3=0.f;
        #pragma unroll
        for (int q = 0; q < 24; q++) {
            float4 w4 = wv4[q];
            float4 xa = x0[q], xb = x1[q], xc = x2[q], xd = x3[q];
            a0 += w4.x*xa.x + w4.y*xa.y + w4.z*xa.z + w4.w*xa.w;
            a1 += w4.x*xb.x + w4.y*xb.y + w4.z*xb.z + w4.w*xb.w;
            a2 += w4.x*xc.x + w4.y*xc.y + w4.z*xc.z + w4.w*xc.w;
            a3 += w4.x*xd.x + w4.y*xd.y + w4.z*xd.z + w4.w*xd.w;
        }
        float4 o = make_float4(a0,a1,a2,a3);
        *reinterpret_cast<float4*>(&g_v[(b*Cc + c)*Ls + l0 + l]) = o;
    }
}

// ---------------- K1b: per-plane 64x64 transpose -> g_vw ---------------------
__global__ void k_tr()
{
    __shared__ float s[64][65];
    int plane = blockIdx.x;             // b*Cc + c  (192 planes)
    const float* src = &g_v[plane*Ls];
    float*       dst = &g_vw[plane*Ls];
    int tid = threadIdx.x;              // 256
    for (int idx = tid; idx < 4096; idx += 256)
        s[idx>>6][idx&63] = src[idx];
    __syncthreads();
    for (int idx = tid; idx < 4096; idx += 256)
        dst[idx] = s[idx&63][idx>>6];   // dst[w*64+h] = v[h*64+w]
}

// ---------------- K2: projections + fused local scan (pass A + y_local) ------
// sxd layout: B states cols 0..15, C states cols 16..31, dt-rank cols 32..37
__global__ void k_proj(const float* __restrict__ x_proj_w,
                       const float* __restrict__ dt_w,
                       const float* __restrict__ dt_b)
{
    __shared__ float sxs[32][100];   // 12.8 KB
    __shared__ float swp[38][100];   // 15.2 KB
    __shared__ float sxd[32][48];    //  6.1 KB

    int tiles = Ls/32;
    int tile = blockIdx.x % tiles;
    int k    = (blockIdx.x / tiles) % Kk;
    int b    = blockIdx.x / (tiles*Kk);
    int tid  = threadIdx.x;   // 192
    int c    = tid % 96;
    int half = tid / 96;
    int t0   = tile*32;

    for (int idx = tid; idx < 38*96; idx += 192)
        swp[idx/96][idx%96] = x_proj_w[k*38*96 + idx];
    float wdt[6];
    #pragma unroll
    for (int r = 0; r < 6; r++) wdt[r] = dt_w[(k*Cc + c)*Rr + r];
    float dtb = dt_b[k*Cc + c];
    int   kc  = k*Cc + c;
    float A0  = g_A0[kc];
    bool  fast = (g_fastf[kc] != 0.0f);

    // per-thread contiguous row loads in scan order (each half loads 16 rows)
    const float* srcp = ((k & 1) ? g_vw : g_v) + (b*Cc + c)*Ls;
    if (k < 2) {
        const float4* p4 = reinterpret_cast<const float4*>(srcp + t0 + half*16);
        #pragma unroll
        for (int j = 0; j < 4; j++) {
            float4 v4 = p4[j];
            int r0 = half*16 + 4*j;
            sxs[r0+0][c]=v4.x; sxs[r0+1][c]=v4.y; sxs[r0+2][c]=v4.z; sxs[r0+3][c]=v4.w;
        }
    } else {
        const float4* p4 = reinterpret_cast<const float4*>(srcp + (4096 - t0 - 32) + half*16);
        #pragma unroll
        for (int j = 0; j < 4; j++) {
            float4 v4 = p4[j];
            int ib = 31 - (half*16 + 4*j);
            sxs[ib][c]=v4.x; sxs[ib-1][c]=v4.y; sxs[ib-2][c]=v4.z; sxs[ib-3][c]=v4.w;
        }
    }
    __syncthreads();

    // x_dbl = xs @ x_proj_w^T — register-tiled 2j x 4i, float4 over cp
    if (tid < 152) {
        int jp = tid % 19, ig = tid / 19;
        int j0 = jp*2, i0 = ig*4;
        const float4* w0 = reinterpret_cast<const float4*>(&swp[j0][0]);
        const float4* w1 = reinterpret_cast<const float4*>(&swp[j0+1][0]);
        const float4* xA = reinterpret_cast<const float4*>(&sxs[i0+0][0]);
        const float4* xB = reinterpret_cast<const float4*>(&sxs[i0+1][0]);
        const float4* xC = reinterpret_cast<const float4*>(&sxs[i0+2][0]);
        const float4* xD = reinterpret_cast<const float4*>(&sxs[i0+3][0]);
        float a00=0.f,a01=0.f,a02=0.f,a03=0.f;
        float a10=0.f,a11=0.f,a12=0.f,a13=0.f;
        #pragma unroll
        for (int q = 0; q < 24; q++) {
            float4 wa = w0[q], wb = w1[q];
            float4 xa = xA[q], xb = xB[q], xc = xC[q], xd = xD[q];
            a00 += wa.x*xa.x + wa.y*xa.y + wa.z*xa.z + wa.w*xa.w;
            a01 += wa.x*xb.x + wa.y*xb.y + wa.z*xb.z + wa.w*xb.w;
            a02 += wa.x*xc.x + wa.y*xc.y + wa.z*xc.z + wa.w*xc.w;
            a03 += wa.x*xd.x + wa.y*xd.y + wa.z*xd.z + wa.w*xd.w;
            a10 += wb.x*xa.x + wb.y*xa.y + wb.z*xa.z + wb.w*xa.w;
            a11 += wb.x*xb.x + wb.y*xb.y + wb.z*xb.z + wb.w*xb.w;
            a12 += wb.x*xc.x + wb.y*xc.y + wb.z*xc.z + wb.w*xc.w;
            a13 += wb.x*xd.x + wb.y*xd.y + wb.z*xd.z + wb.w*xd.w;
        }
        int nc0 = (j0 < 6) ? 32 + j0 : j0 - 6;   // pairs never straddle 6
        int nc1 = nc0 + 1;
        sxd[i0+0][nc0]=a00; sxd[i0+1][nc0]=a01; sxd[i0+2][nc0]=a02; sxd[i0+3][nc0]=a03;
        sxd[i0+0][nc1]=a10; sxd[i0+1][nc1]=a11; sxd[i0+2][nc1]=a12; sxd[i0+3][nc1]=a13;
    }
    __syncthreads();

    int bk = b*Kk + k;
    // fused local scan: this half-tile IS segment (tile*2 + half), h0 = 0
    float h[16];
    #pragma unroll
    for (int n = 0; n < 16; n++) h[n] = 0.f;
    float cum = 0.f;
    float Wrun = 1.f;

    #pragma unroll
    for (int ii = 0; ii < 16; ii++) {
        int i = half*16 + ii;
        float acc = dtb;
        #pragma unroll
        for (int r = 0; r < 6; r++) acc += sxd[i][32+r]*wdt[r];
        float delta = (acc > 20.f) ? acc : log1pf(__expf(acc));
        cum += delta;
        float du = delta * sxs[i][c];
        float w = __expf(delta * A0);
        Wrun *= w;
        float dA[16];
        if (fast) {
            float w2 = w*w, w4 = w2*w2, w8 = w4*w4;
            dA[0]=w;      dA[1]=w2;     dA[2]=w2*w;    dA[3]=w4;
            dA[4]=w4*w;   dA[5]=w4*w2;  dA[6]=dA[5]*w; dA[7]=w8;
            #pragma unroll
            for (int n = 0; n < 8; n++) dA[8+n] = w8*dA[n];
        } else {
            #pragma unroll
            for (int n = 0; n < 16; n++) dA[n] = __expf(delta * g_An[kc*Nn + n]);
        }
        float4 B0 = *reinterpret_cast<const float4*>(&sxd[i][0]);
        float4 B1 = *reinterpret_cast<const float4*>(&sxd[i][4]);
        float4 B2 = *reinterpret_cast<const float4*>(&sxd[i][8]);
        float4 B3 = *reinterpret_cast<const float4*>(&sxd[i][12]);
        h[0]=dA[0]*h[0]+du*B0.x;  h[1]=dA[1]*h[1]+du*B0.y;
        h[2]=dA[2]*h[2]+du*B0.z;  h[3]=dA[3]*h[3]+du*B0.w;
        h[4]=dA[4]*h[4]+du*B1.x;  h[5]=dA[5]*h[5]+du*B1.y;
        h[6]=dA[6]*h[6]+du*B1.z;  h[7]=dA[7]*h[7]+du*B1.w;
        h[8]=dA[8]*h[8]+du*B2.x;  h[9]=dA[9]*h[9]+du*B2.y;
        h[10]=dA[10]*h[10]+du*B2.z; h[11]=dA[11]*h[11]+du*B2.w;
        h[12]=dA[12]*h[12]+du*B3.x; h[13]=dA[13]*h[13]+du*B3.y;
        h[14]=dA[14]*h[14]+du*B3.z; h[15]=dA[15]*h[15]+du*B3.w;

        float4 C0 = *reinterpret_cast<const float4*>(&sxd[i][16]);
        float4 C1 = *reinterpret_cast<const float4*>(&sxd[i][20]);
        float4 C2 = *reinterpret_cast<const float4*>(&sxd[i][24]);
        float4 C3 = *reinterpret_cast<const float4*>(&sxd[i][28]);
        float y0 = h[0]*C0.x + h[1]*C0.y + h[2]*C0.z + h[3]*C0.w;
        float y1 = h[4]*C1.x + h[5]*C1.y + h[6]*C1.z + h[7]*C1.w;
        float y2 = h[8]*C2.x + h[9]*C2.y + h[10]*C2.z + h[11]*C2.w;
        float y3 = h[12]*C3.x + h[13]*C3.y + h[14]*C3.z + h[15]*C3.w;

        int gi = (bk*Ls + t0 + i);
        g_y[gi*Cc + c] = (y0+y1) + (y2+y3);
        g_W[gi*Cc + c] = Wrun;
    }

    int hb = (bk*Sseg + tile*2 + half)*Cc + c;
    g_sumd[hb] = cum;
    float4* hp = reinterpret_cast<float4*>(&g_hend[hb*Nn]);
    #pragma unroll
    for (int q = 0; q < 4; q++)
        hp[q] = make_float4(h[4*q], h[4*q+1], h[4*q+2], h[4*q+3]);

    // store C for the correction kernel (float4: cols 16..31)
    if (tid < 128) {
        int i = tid >> 2, q = tid & 3;
        int gi = (bk*Ls + t0 + i);
        reinterpret_cast<float4*>(g_Cv)[gi*4 + q] =
            *reinterpret_cast<const float4*>(&sxd[i][16 + 4*q]);
    }
}

// ---------------- K3b: combine — per-channel block-staged affine scan --------
// one block (256 thr) per (bk, c). 16 groups x 16 segments; 1 exp per segment.
__global__ void k_combine()
{
    __shared__ float sE[Sseg][17];    // hend, then h0 (in place) ~17 KB
    __shared__ float sW[Sseg];        // w = exp(A0*sumd)
    __shared__ float sSd[Sseg];       // sumd (non-fast fallback)
    __shared__ float sA[16][17];
    __shared__ float sB[16][17];
    __shared__ float sH[16][17];

    int bk = blockIdx.x / Cc;         // 0..7
    int c  = blockIdx.x % Cc;
    int k  = bk & 3;
    int tid = threadIdx.x;            // 256
    float A0 = g_A0[k*Cc + c];

    for (int p = tid; p < Sseg*16; p += 256) {
        int s = p >> 4, j = p & 15;
        sE[s][j] = g_hend[((bk*Sseg + s)*Cc + c)*Nn + j];
    }
    for (int s = tid; s < Sseg; s += 256) {
        float sd = g_sumd[(bk*Sseg + s)*Cc + c];
        sSd[s] = sd;
        sW[s]  = __expf(A0 * sd);
    }
    __syncthreads();

    int n = tid & 15;                 // chain (state index)
    int g = tid >> 4;                 // segment group 0..15 (16 segs each)
    int m = n + 1;                    // power
    bool fast = (g_fastf[k*Cc + c] != 0.0f);
    float An  = g_An[(k*Cc + c)*Nn + n];
    int sbase = g*16;

    float P[16];
    if (fast) {
        #pragma unroll
        for (int j = 0; j < 16; j++) {
            float w = sW[sbase + j];
            float w2 = w*w, w4 = w2*w2, w8 = w4*w4, w16 = w8*w8;
            float p = 1.f;
            if (m & 1)  p *= w;
            if (m & 2)  p *= w2;
            if (m & 4)  p *= w4;
            if (m & 8)  p *= w8;
            if (m & 16) p *= w16;
            P[j] = p;
        }
    } else {
        #pragma unroll
        for (int j = 0; j < 16; j++) P[j] = __expf(An * sSd[sbase + j]);
    }

    float A = 1.f, Bv = 0.f;
    #pragma unroll
    for (int j = 0; j < 16; j++) { Bv = P[j]*Bv + sE[sbase + j][n]; A *= P[j]; }
    sA[g][n] = A; sB[g][n] = Bv;
    __syncthreads();

    if (tid < 16) {
        float h = 0.f;
        #pragma unroll
        for (int gg = 0; gg < 16; gg++) {
            sH[gg][tid] = h;
            h = sA[gg][tid]*h + sB[gg][tid];
        }
    }
    __syncthreads();

    float h = sH[g][n];
    #pragma unroll
    for (int j = 0; j < 16; j++) {
        float e = sE[sbase + j][n];
        sE[sbase + j][n] = h;
        h = P[j]*h + e;
    }
    __syncthreads();

    for (int p = tid; p < Sseg*16; p += 256) {
        int s = p >> 4, j = p & 15;
        g_h0[((bk*Sseg + s)*Cc + c)*Nn + j] = sE[s][j];
    }
}

// ---------------- K4: parallel y correction (2 segments per block) -----------
__global__ void k_ycorr()
{
    __shared__ float4 sC4[2][Tseg][4];

    int segp = blockIdx.x & 127;      // segment pair
    int bk   = blockIdx.x >> 7;
    int k    = bk & 3;
    int tid  = threadIdx.x;           // 192
    int c    = tid % 96;
    int sub  = tid / 96;              // 0/1
    int seg  = segp*2 + sub;
    int base = bk*Ls + seg*Tseg;
    int kc   = k*Cc + c;

    for (int idx = c; idx < Tseg*4; idx += 96) {
        int i = idx >> 2, q = idx & 3;
        sC4[sub][i][q] = reinterpret_cast<const float4*>(g_Cv)[(base + i)*4 + q];
    }

    float A0   = g_A0[kc];
    bool  fast = (g_fastf[kc] != 0.0f);
    float invA0 = 1.0f / A0;
    float An[16];
    if (!fast) {
        #pragma unroll
        for (int n = 0; n < 16; n++) An[n] = g_An[kc*Nn + n];
    }

    float h0[16];
    {
        const float4* h0p = reinterpret_cast<const float4*>(
            &g_h0[((bk*Sseg + seg)*Cc + c)*Nn]);
        #pragma unroll
        for (int q = 0; q < 4; q++) {
            float4 t = h0p[q];
            h0[4*q]=t.x; h0[4*q+1]=t.y; h0[4*q+2]=t.z; h0[4*q+3]=t.w;
        }
    }
    __syncthreads();

    #pragma unroll
    for (int i = 0; i < Tseg; i++) {
        float w = g_W[(base + i)*Cc + c];   // = exp(A0 * cum)
        float dA[16];
        if (fast) {
            float w2 = w*w, w4 = w2*w2, w8 = w4*w4;
            dA[0]=w;      dA[1]=w2;     dA[2]=w2*w;    dA[3]=w4;
            dA[4]=w4*w;   dA[5]=w4*w2;  dA[6]=dA[5]*w; dA[7]=w8;
            #pragma unroll
            for (int n = 0; n < 8; n++) dA[8+n] = w8*dA[n];
        } else {
            float cum = __logf(w) * invA0;
            #pragma unroll
            for (int n = 0; n < 16; n++) dA[n] = __expf(cum * An[n]);
        }
        const float* Cp = reinterpret_cast<const float*>(&sC4[sub][i][0]);
        float y0=0.f,y1=0.f,y2=0.f,y3=0.f;
        #pragma unroll
        for (int n = 0; n < 16; n += 4) {
            y0 += dA[n+0]*h0[n+0]*Cp[n+0];
            y1 += dA[n+1]*h0[n+1]*Cp[n+1];
            y2 += dA[n+2]*h0[n+2]*Cp[n+2];
            y3 += dA[n+3]*h0[n+3]*Cp[n+3];
        }
        g_y[(base + i)*Cc + c] += (y0+y1) + (y2+y3);
    }
}

// ---------------- K5: depthwise 3x3 + BN + GELU + pooled sum -----------------
__global__ void k_conv(const float* __restrict__ dw_w, const float* __restrict__ dw_b,
                       const float* __restrict__ bn1_g, const float* __restrict__ bn1_b)
{
    __shared__ float sIm[66][66];
    __shared__ float red[256];
    int b = blockIdx.x / Cc;
    int c = blockIdx.x % Cc;
    int tid = threadIdx.x; // 256 threads

    for (int idx = tid; idx < 66*66; idx += 256)
        (&sIm[0][0])[idx] = 0.f;
    __syncthreads();
    const float* vp = &g_v[(b*Cc + c)*Ls];
    for (int idx = tid; idx < Ls; idx += 256)
        sIm[(idx>>6) + 1][(idx & 63) + 1] = vp[idx];

    float wgt[9];
    #pragma unroll
    for (int j = 0; j < 9; j++) wgt[j] = dw_w[c*9 + j];
    float bias = dw_b[c];
    float s1 = bn1_g[c] * rsqrtf(1.0f + 1e-5f);
    float sh = bn1_b[c];
    __syncthreads();

    float lsum = 0.f;
    for (int idx = tid; idx < Ls; idx += 256) {
        int hh = idx >> 6, ww = idx & 63;
        float acc = 0.f;
        #pragma unroll
        for (int dy = 0; dy < 3; dy++)
            #pragma unroll
            for (int dx = 0; dx < 3; dx++)
                acc += sIm[hh+dy][ww+dx]*wgt[dy*3+dx];
        float xv = (acc + bias)*s1 + sh;
        float gl = xv * normcdff(xv);
        g_convx[(b*Cc + c)*Ls + idx] = gl;
        lsum += gl;
    }
    red[tid] = lsum;
    __syncthreads();
    for (int s = 128; s > 0; s >>= 1) {
        if (tid < s) red[tid] += red[tid + s];
        __syncthreads();
    }
    if (tid == 0) g_pool[b*Cc + c] = red[0];
}

// ---------------- K6: dirs + gates + output GEMM (fused, dynamic smem) -------
__global__ void k_attout(const float* __restrict__ Ds,
                      const float* __restrict__ ci_w1, const float* __restrict__ ci_b1,
                      const float* __restrict__ ci_bn_g, const float* __restrict__ ci_bn_b,
                      const float* __restrict__ ci_w2, const float* __restrict__ ci_b2,
                      const float* __restrict__ si_w1, const float* __restrict__ si_b1,
                      const float* __restrict__ si_bn_g, const float* __restrict__ si_bn_b,
                      const float* __restrict__ si_w2, const float* __restrict__ si_b2,
                      const float* __restrict__ proj_w, const float* __restrict__ proj_b,
                      float* __restrict__ out)
{
    extern __shared__ float dsm[];
    float (*sAtt)[97]   = (float(*)[97])dsm;                          // 32*97
    float (*sV)[33]     = (float(*)[33])(dsm + 32*97);                // 96*33
    float (*sCx)[33]    = (float(*)[33])(dsm + 32*97 + 96*33);        // 96*33
    float (*sProjT)[97] = (float(*)[97])(dsm + 32*97 + 2*96*33);      // 96*97
    __shared__ float spool[96];
    __shared__ float szc[12];
    __shared__ float ssw[6][96];
    __shared__ float st1[32][8];
    __shared__ float sml[32];

    int tiles = Ls/32; // 128
    int b  = blockIdx.x / tiles;
    int l0 = (blockIdx.x % tiles)*32;
    int tid = threadIdx.x; // 192
    int c    = tid % 96;
    int half = tid / 96;

    if (half == 0) spool[c] = g_pool[b*Cc + c] * (1.0f/4096.0f);
    for (int idx = tid; idx < 6*96; idx += 192)
        (&ssw[0][0])[idx] = si_w1[idx];
    for (int idx = tid; idx < 96*96; idx += 192)
        sProjT[idx % 96][idx / 96] = proj_w[idx];   // [cp][c_out]

    {   // own-column contiguous row loads (each half loads 16 of 32)
        const float4* vp = reinterpret_cast<const float4*>(&g_v[(b*Cc+c)*Ls + l0 + half*16]);
        const float4* cp = reinterpret_cast<const float4*>(&g_convx[(b*Cc+c)*Ls + l0 + half*16]);
        #pragma unroll
        for (int j = 0; j < 4; j++) {
            int r0 = half*16 + 4*j;
            float4 t = vp[j];
            sV[c][r0]=t.x; sV[c][r0+1]=t.y; sV[c][r0+2]=t.z; sV[c][r0+3]=t.w;
            float4 u = cp[j];
            sCx[c][r0]=u.x; sCx[c][r0+1]=u.y; sCx[c][r0+2]=u.z; sCx[c][r0+3]=u.w;
        }
    }
    __syncthreads();

    float Dsum = Ds[c] + Ds[Cc + c] + Ds[2*Cc + c] + Ds[3*Cc + c];
    int hh = l0 >> 6, ww0 = l0 & 63;
    int b4 = b*Kk;
    #pragma unroll
    for (int ii = 0; ii < 16; ii++) {
        int i = half*16 + ii;
        int l = l0 + i;
        int t1 = (ww0 + i)*64 + hh;
        float att =
            g_y[((b4+0)*Ls + l)*Cc + c] +
            g_y[((b4+1)*Ls + t1)*Cc + c] +
            g_y[((b4+2)*Ls + (4095 - l))*Cc + c] +
            g_y[((b4+3)*Ls + (4095 - t1))*Cc + c] +
            Dsum * sV[c][i];
        sAtt[i][c] = att;
    }
    __syncthreads();

    if (tid < 12) {
        float acc = ci_b1[tid];
        #pragma unroll
        for (int cp = 0; cp < 96; cp++) acc += ci_w1[tid*96 + cp]*spool[cp];
        float z = acc * (ci_bn_g[tid]*rsqrtf(1.0f + 1e-5f)) + ci_bn_b[tid];
        szc[tid] = z * normcdff(z);
    }
    {
        int i = tid / 6, j = tid % 6;
        float acc = si_b1[j];
        #pragma unroll
        for (int cp = 0; cp < 96; cp++) acc += sAtt[i][cp]*ssw[j][cp];
        float z = acc * (si_bn_g[j]*rsqrtf(1.0f + 1e-5f)) + si_bn_b[j];
        st1[i][j] = z * normcdff(z);
    }
    __syncthreads();

    float cmv = ci_b2[c];
    #pragma unroll
    for (int j = 0; j < 12; j++) cmv += ci_w2[c*12 + j]*szc[j];
    float cms = sigmoidf_(cmv);
    if (tid < 32) {
        float sm = si_b2[0];
        #pragma unroll
        for (int j = 0; j < 6; j++) sm += st1[tid][j]*si_w2[j];
        sml[tid] = sigmoidf_(sm);
    }
    __syncthreads();

    #pragma unroll
    for (int ii = 0; ii < 16; ii++) {
        int i = half*16 + ii;
        sAtt[i][c] = sAtt[i][c]*cms + sml[i]*sCx[c][i];
    }
    __syncthreads();

    float pb = proj_b[c];
    for (int i = half*16; i < half*16 + 16; i += 4) {
        float a0=pb,a1=pb,a2=pb,a3=pb;
        #pragma unroll
        for (int cp = 0; cp < 96; cp++) {
            float wv = sProjT[cp][c];
            a0 += sAtt[i+0][cp]*wv;
            a1 += sAtt[i+1][cp]*wv;
            a2 += sAtt[i+2][cp]*wv;
            a3 += sAtt[i+3][cp]*wv;
        }
        out[(b*Ls + l0 + i+0)*Cc + c] = a0;
        out[(b*Ls + l0 + i+1)*Cc + c] = a1;
        out[(b*Ls + l0 + i+2)*Cc + c] = a2;
        out[(b*Ls + l0 + i+3)*Cc + c] = a3;
    }
}

// ---------------- launcher ----------------------------------------------------
extern "C" void kernel_launch(void* const* d_in, const int* in_sizes, int n_in,
                              void* d_out, int out_size)
{
    const float* x        = (const float*)d_in[0];
    const float* qkv_w    = (const float*)d_in[3];
    const float* proj_w   = (const float*)d_in[4];
    const float* proj_b   = (const float*)d_in[5];
    const float* dw_w     = (const float*)d_in[6];
    const float* dw_b     = (const float*)d_in[7];
    const float* bn1_g    = (const float*)d_in[8];
    const float* bn1_b    = (const float*)d_in[9];
    const float* ci_w1    = (const float*)d_in[10];
    const float* ci_b1    = (const float*)d_in[11];
    const float* ci_bn_g  = (const float*)d_in[12];
    const float* ci_bn_b  = (const float*)d_in[13];
    const float* ci_w2    = (const float*)d_in[14];
    const float* ci_b2    = (const float*)d_in[15];
    const float* si_w1    = (const float*)d_in[16];
    const float* si_b1    = (const float*)d_in[17];
    const float* si_bn_g  = (const float*)d_in[18];
    const float* si_bn_b  = (const float*)d_in[19];
    const float* si_w2    = (const float*)d_in[20];
    const float* si_b2    = (const float*)d_in[21];
    const float* x_proj_w = (const float*)d_in[22];
    const float* dt_w     = (const float*)d_in[23];
    const float* dt_b     = (const float*)d_in[24];
    const float* A_logs   = (const float*)d_in[25];
    const float* Ds       = (const float*)d_in[26];
    float* out = (float*)d_out;

    const int ATTOUT_SMEM = (32*97 + 2*96*33 + 96*97) * 4;  // 75008 B
    cudaFuncSetAttribute(k_attout, cudaFuncAttributeMaxDynamicSharedMemorySize,
                         ATTOUT_SMEM);

    k_qkv<<<Bsz*(Ls/32) + 1, 192>>>(x, qkv_w, A_logs);
    k_tr<<<Bsz*Cc, 256>>>();
    k_proj<<<Bsz*Kk*(Ls/32), 192>>>(x_proj_w, dt_w, dt_b);
    k_combine<<<Bsz*Kk*Cc, 256>>>();
    k_ycorr<<<Bsz*Kk*(Sseg/2), 192>>>();
    k_conv<<<Bsz*Cc, 256>>>(dw_w, dw_b, bn1_g, bn1_b);
    k_attout<<<Bsz*(Ls/32), 192, ATTOUT_SMEM>>>(Ds,
        ci_w1, ci_b1, ci_bn_g, ci_bn_b, ci_w2, ci_b2,
        si_w1, si_b1, si_bn_g, si_bn_b, si_w2, si_b2,
        proj_w, proj_b, out);
}